// round 16
// baseline (speedup 1.0000x reference)
#include <cuda_runtime.h>
#include <cuda_bf16.h>
#include <cstdint>

// Problem constants (fixed by the dataset's setup_inputs)
#define NNODES 100000
#define NEDGES 50000
#define EDGESZ 16
#define NMEMB  (NEDGES * EDGESZ)   // 800000
#define DIM    128

// Scratch (allocation-free rule: __device__ globals). Vector-accessed arrays
// are DECLARED as float4 so 16-byte alignment is guaranteed by type.
// Zero-initialized at load; kE's epilogue re-zeroes counters.
__device__ float4 g_es4[((size_t)NEDGES * DIM) / 4];   // edge_sum
__device__ float4 g_AH4[((size_t)NNODES * DIM) / 4];   // AH
__device__ float  g_w2[NNODES];
__device__ int    g_deg[NNODES];
__device__ int    g_cnt[NNODES];
__device__ int    g_off[NNODES];
__device__ int    g_elist[NMEMB];   // node -> list of incident edges
__device__ int    g_ctr;

// ---------------------------------------------------------------------------
// packed f32x2 helpers
// ---------------------------------------------------------------------------
__device__ __forceinline__ void fma2(unsigned long long& d,
                                     unsigned long long a, unsigned long long b)
{
    asm("fma.rn.f32x2 %0, %1, %2, %0;" : "+l"(d) : "l"(a), "l"(b));
}
__device__ __forceinline__ unsigned long long pk2(float lo, float hi)
{
    unsigned long long r;
    asm("mov.b64 %0, {%1, %2};" : "=l"(r) : "f"(lo), "f"(hi));
    return r;
}
__device__ __forceinline__ void unpk2(float& lo, float& hi, unsigned long long v)
{
    asm("mov.b64 {%0, %1}, %2;" : "=f"(lo), "=f"(hi) : "l"(v));
}

// ---------------------------------------------------------------------------
// Kernel W: per-node MLP -> w2[n]  AND  membership degree histogram.
// NMEMB/8 == NNODES, so thread n also histograms memberships [8n, 8n+8).
// ---------------------------------------------------------------------------
__global__ __launch_bounds__(256) void kW(
    const float* __restrict__ iw, const int* __restrict__ mn,
    const float* __restrict__ fc1w, const float* __restrict__ fc1b,
    const float* __restrict__ fc2w, const float* __restrict__ fc2b,
    const float* __restrict__ fc3w, const float* __restrict__ fc3b)
{
    int n = blockIdx.x * 256 + threadIdx.x;
    if (n >= NNODES) return;
    float x0 = iw[n * 2 + 0];
    float x1 = iw[n * 2 + 1];
    float h1[10];
#pragma unroll
    for (int j = 0; j < 10; j++)
        h1[j] = fmaxf(0.f, fmaf(x0, fc1w[j], fmaf(x1, fc1w[10 + j], fc1b[j])));
    float h2[5];
#pragma unroll
    for (int j = 0; j < 5; j++) {
        float s = fc2b[j];
#pragma unroll
        for (int k = 0; k < 10; k++) s = fmaf(h1[k], fc2w[k * 5 + j], s);
        h2[j] = fmaxf(0.f, s);
    }
    float z = fc3b[0];
#pragma unroll
    for (int k = 0; k < 5; k++) z = fmaf(h2[k], fc3w[k], z);
    g_w2[n] = 1.f / (1.f + expf(-z));

    // degree histogram: 8 memberships per thread (2 x int4)
    const int4* mn4 = reinterpret_cast<const int4*>(mn);
    int4 a = mn4[n * 2 + 0];
    int4 b = mn4[n * 2 + 1];
    atomicAdd(&g_deg[a.x], 1);
    atomicAdd(&g_deg[a.y], 1);
    atomicAdd(&g_deg[a.z], 1);
    atomicAdd(&g_deg[a.w], 1);
    atomicAdd(&g_deg[b.x], 1);
    atomicAdd(&g_deg[b.y], 1);
    atomicAdd(&g_deg[b.z], 1);
    atomicAdd(&g_deg[b.w], 1);
}

// ---------------------------------------------------------------------------
// Kernel Off: per-node segment offsets via warp-aggregated atomic counter
// (depends only on kW's histogram)
// ---------------------------------------------------------------------------
__global__ __launch_bounds__(256) void kOff()
{
    int n = blockIdx.x * 256 + threadIdx.x;
    int lane = threadIdx.x & 31;
    int deg = (n < NNODES) ? g_deg[n] : 0;
    int x = deg;
#pragma unroll
    for (int o = 1; o < 32; o <<= 1) {
        int y = __shfl_up_sync(0xffffffffu, x, o);
        if (lane >= o) x += y;
    }
    int total = __shfl_sync(0xffffffffu, x, 31);
    int base = 0;
    if (lane == 0) base = atomicAdd(&g_ctr, total);
    base = __shfl_sync(0xffffffffu, base, 0);
    if (n < NNODES) g_off[n] = base + x - deg;
}

// ---------------------------------------------------------------------------
// Scatter: node -> incident-edge list (edge id == membership >> 4).
// One membership per thread (measured faster than int4 batching).
// Arrival order racy; kF's stable sort makes the result deterministic.
// ---------------------------------------------------------------------------
__global__ __launch_bounds__(256) void kScat(const int* __restrict__ mn)
{
    int m = blockIdx.x * 256 + threadIdx.x;
    if (m >= NMEMB) return;
    int node = mn[m];
    int pos = g_off[node] + atomicAdd(&g_cnt[node], 1);
    g_elist[pos] = m >> 4;
}

// ---------------------------------------------------------------------------
// Kernel B: edge_sum[e] = sum_m (H[m]*w2[m]). (histogram moved to kW)
// grid = NEDGES blocks x 128 threads       <-- ncu launch index 3
// ---------------------------------------------------------------------------
__global__ __launch_bounds__(128) void kB(const int* __restrict__ mn,
                                          const float* __restrict__ H)
{
    float* es = reinterpret_cast<float*>(g_es4);
    int e = blockIdx.x;
    __shared__ int   mem[EDGESZ];
    __shared__ float w2e[EDGESZ];
    int t = threadIdx.x;
    if (t < EDGESZ) {
        int node = mn[e * EDGESZ + t];
        mem[t] = node;
        w2e[t] = g_w2[node];
    }
    __syncthreads();
    float s = 0.f;
#pragma unroll
    for (int i = 0; i < EDGESZ; i++)
        s = __fadd_rn(s, __fmul_rn(H[(size_t)mem[i] * DIM + t], w2e[i]));
    es[(size_t)e * DIM + t] = s;
}

// ---------------------------------------------------------------------------
// Kernel F: one WARP per node. STABLE register rank-sort of edge segment
// (duplicate edge ids possible when a node repeats within one edge — the
// (ej == e && j < lane) tie-break is load-bearing), 4-batched float4 gather
// per lane (guaranteed MLP>=4), double warp rowsum, AH store.
// grid = NNODES/8 blocks x 256 threads (8 warps)
// ---------------------------------------------------------------------------
__global__ __launch_bounds__(256) void kF(const float* __restrict__ H)
{
    __shared__ int ss[8 * 128];            // per-warp sorted edge ids
    int t = threadIdx.x;
    int w = t >> 5, lane = t & 31;
    int n = blockIdx.x * 8 + w;
    int* ssw = ss + w * 128;

    int deg = g_deg[n];
    int st  = g_off[n];
    const float inv15 = 1.f / 15.f;

    if (deg <= 32) {
        // stable register rank-sort via shuffles (duplicates get distinct ranks)
        int e = (lane < deg) ? g_elist[st + lane] : 0x7FFFFFFF;
        int rank = 0;
        for (int j = 0; j < deg; j++) {
            int ej = __shfl_sync(0xffffffffu, e, j);
            rank += (ej < e) || (ej == e && j < lane);
        }
        if (lane < deg) ssw[rank] = e;
    } else {
        // (practically unreachable) lane-0 insertion sort in smem (stable)
        if (lane == 0) {
            int d = deg < 128 ? deg : 128;
            for (int i = 0; i < d; i++) ssw[i] = g_elist[st + i];
            for (int i = 1; i < d; i++) {
                int key = ssw[i]; int j = i - 1;
                while (j >= 0 && ssw[j] > key) { ssw[j + 1] = ssw[j]; j--; }
                ssw[j + 1] = key;
            }
        }
    }
    __syncwarp();
    int dg = deg > 128 ? 128 : deg;

    // Gather in ascending-edge order. Loads batched 4-wide (independent);
    // per-column adds remain strictly sequential (bit-identical to R15).
    float s0 = 0.f, s1 = 0.f, s2 = 0.f, s3 = 0.f;
    int j = 0;
    for (; j + 4 <= dg; j += 4) {
        float4 v0 = g_es4[(size_t)ssw[j + 0] * (DIM / 4) + lane];
        float4 v1 = g_es4[(size_t)ssw[j + 1] * (DIM / 4) + lane];
        float4 v2 = g_es4[(size_t)ssw[j + 2] * (DIM / 4) + lane];
        float4 v3 = g_es4[(size_t)ssw[j + 3] * (DIM / 4) + lane];
        s0 = __fadd_rn(__fadd_rn(__fadd_rn(__fadd_rn(s0, v0.x), v1.x), v2.x), v3.x);
        s1 = __fadd_rn(__fadd_rn(__fadd_rn(__fadd_rn(s1, v0.y), v1.y), v2.y), v3.y);
        s2 = __fadd_rn(__fadd_rn(__fadd_rn(__fadd_rn(s2, v0.z), v1.z), v2.z), v3.z);
        s3 = __fadd_rn(__fadd_rn(__fadd_rn(__fadd_rn(s3, v0.w), v1.w), v2.w), v3.w);
    }
    for (; j < dg; j++) {
        float4 v = g_es4[(size_t)ssw[j] * (DIM / 4) + lane];
        s0 = __fadd_rn(s0, v.x);
        s1 = __fadd_rn(s1, v.y);
        s2 = __fadd_rn(s2, v.z);
        s3 = __fadd_rn(s3, v.w);
    }

    const float* hrow = H + (size_t)n * DIM + lane * 4;
    float coef = 1.f - (float)deg * inv15;
    float4 nv;
    nv.x = fmaf(hrow[0], coef, s0 * inv15);
    nv.y = fmaf(hrow[1], coef, s1 * inv15);
    nv.z = fmaf(hrow[2], coef, s2 * inv15);
    nv.w = fmaf(hrow[3], coef, s3 * inv15);

    // double-precision rowsum across the warp (order-insensitive at 1e-16)
    double d = ((double)nv.x + (double)nv.y) + ((double)nv.z + (double)nv.w);
#pragma unroll
    for (int o = 16; o > 0; o >>= 1)
        d += __shfl_xor_sync(0xffffffffu, d, o);
    float rinv = (d != 0.0) ? (float)(1.0 / d) : 0.f;

    float4 ov;
    ov.x = __fmul_rn(nv.x, rinv);
    ov.y = __fmul_rn(nv.y, rinv);
    ov.z = __fmul_rn(nv.z, rinv);
    ov.w = __fmul_rn(nv.w, rinv);
    g_AH4[(size_t)n * (DIM / 4) + lane] = ov;
}

// ---------------------------------------------------------------------------
// Kernel E: out = AH @ W + bias, packed f32x2 FFMA.
// block = 128 threads handles 32 rows; thread owns output column t.
// Epilogue re-zeroes deg/cnt/ctr for the next call.
// ---------------------------------------------------------------------------
__global__ __launch_bounds__(128) void kE(const float* __restrict__ W,
                                          const float* __restrict__ bias,
                                          float* __restrict__ out)
{
    __shared__ float4 sA4[32 * DIM / 4];
    float* sA = reinterpret_cast<float*>(sA4);
    int t = threadIdx.x;
    size_t base4 = (size_t)blockIdx.x * 32 * (DIM / 4);
#pragma unroll
    for (int i = 0; i < 8; i++) {
        int idx = i * 128 + t;                   // 0 .. 1023 float4s
        sA4[idx] = g_AH4[base4 + idx];
    }
    __syncthreads();

    unsigned long long acc[32];
#pragma unroll
    for (int i = 0; i < 32; i++) acc[i] = 0ull;

#pragma unroll 1
    for (int k = 0; k < DIM; k += 8) {
        unsigned long long wp0 = pk2(W[(k + 0) * DIM + t], W[(k + 1) * DIM + t]);
        unsigned long long wp1 = pk2(W[(k + 2) * DIM + t], W[(k + 3) * DIM + t]);
        unsigned long long wp2 = pk2(W[(k + 4) * DIM + t], W[(k + 5) * DIM + t]);
        unsigned long long wp3 = pk2(W[(k + 6) * DIM + t], W[(k + 7) * DIM + t]);
        const ulonglong2* arow = reinterpret_cast<const ulonglong2*>(sA + k);
#pragma unroll
        for (int i = 0; i < 32; i++) {
            ulonglong2 a0 = arow[i * (DIM / 4)];
            ulonglong2 a1 = arow[i * (DIM / 4) + 1];
            fma2(acc[i], a0.x, wp0);
            fma2(acc[i], a0.y, wp1);
            fma2(acc[i], a1.x, wp2);
            fma2(acc[i], a1.y, wp3);
        }
    }
    float b = bias[t];
    size_t obase = (size_t)blockIdx.x * 32 * DIM;
#pragma unroll
    for (int i = 0; i < 32; i++) {
        float lo, hi;
        unpk2(lo, hi, acc[i]);
        out[obase + (size_t)i * DIM + t] = lo + hi + b;
    }

    // Reset scratch counters for the next call (state invariant across calls)
    int gid = blockIdx.x * 128 + t;
    if (gid < NNODES) {
        g_deg[gid] = 0;
        g_cnt[gid] = 0;
    }
    if (gid == 0) g_ctr = 0;
}

// ---------------------------------------------------------------------------
extern "C" void kernel_launch(void* const* d_in, const int* in_sizes, int n_in,
                              void* d_out, int out_size)
{
    const int*   member_nodes = (const int*)  d_in[0];
    const float* H            = (const float*)d_in[2];
    const float* input_weight = (const float*)d_in[3];
    const float* W            = (const float*)d_in[4];
    const float* bias         = (const float*)d_in[5];
    const float* fc1_w        = (const float*)d_in[6];
    const float* fc1_b        = (const float*)d_in[7];
    const float* fc2_w        = (const float*)d_in[8];
    const float* fc2_b        = (const float*)d_in[9];
    const float* fc3_w        = (const float*)d_in[10];
    const float* fc3_b        = (const float*)d_in[11];
    float* out = (float*)d_out;

    kW<<<(NNODES + 255) / 256, 256>>>(input_weight, member_nodes,
                                      fc1_w, fc1_b, fc2_w, fc2_b, fc3_w, fc3_b);
    kOff<<<(NNODES + 255) / 256, 256>>>();
    kScat<<<(NMEMB + 255) / 256, 256>>>(member_nodes);
    kB<<<NEDGES, 128>>>(member_nodes, H);      // launch index 3 -> ncu target
    kF<<<NNODES / 8, 256>>>(H);
    kE<<<NNODES / 32, 128>>>(W, bias, out);
}

// round 17
// speedup vs baseline: 1.0221x; 1.0221x over previous
#include <cuda_runtime.h>
#include <cuda_bf16.h>
#include <cstdint>

// Problem constants (fixed by the dataset's setup_inputs)
#define NNODES 100000
#define NEDGES 50000
#define EDGESZ 16
#define NMEMB  (NEDGES * EDGESZ)   // 800000
#define DIM    128

// Scratch (allocation-free rule: __device__ globals). Vector-accessed arrays
// are DECLARED as float4 so 16-byte alignment is guaranteed by type.
// Zero-initialized at load; kE's epilogue re-zeroes counters.
__device__ float4 g_es4[((size_t)NEDGES * DIM) / 4];   // edge_sum
__device__ float4 g_AH4[((size_t)NNODES * DIM) / 4];   // AH
__device__ int    g_deg[NNODES];
__device__ int    g_cnt[NNODES];
__device__ int    g_off[NNODES];
__device__ int    g_elist[NMEMB];   // node -> list of incident edges
__device__ int    g_ctr;

// ---------------------------------------------------------------------------
// packed f32x2 helpers
// ---------------------------------------------------------------------------
__device__ __forceinline__ void fma2(unsigned long long& d,
                                     unsigned long long a, unsigned long long b)
{
    asm("fma.rn.f32x2 %0, %1, %2, %0;" : "+l"(d) : "l"(a), "l"(b));
}
__device__ __forceinline__ unsigned long long pk2(float lo, float hi)
{
    unsigned long long r;
    asm("mov.b64 %0, {%1, %2};" : "=l"(r) : "f"(lo), "f"(hi));
    return r;
}
__device__ __forceinline__ void unpk2(float& lo, float& hi, unsigned long long v)
{
    asm("mov.b64 {%0, %1}, %2;" : "=f"(lo), "=f"(hi) : "l"(v));
}

// ---------------------------------------------------------------------------
// Kernel B (self-contained): one WARP per edge.
// Lanes 0-15 compute the member-node MLP (bit-identical fmaf sequence) and
// the degree histogram. All 32 lanes then gather H rows as float4 (lane owns
// 4 columns) with node/w2 broadcast via shfl. Per-column add order identical
// to the scalar version -> bit-identical edge_sum.
// grid = NEDGES/8 blocks x 256 threads (8 warps = 8 edges per block)
// ---------------------------------------------------------------------------
__global__ __launch_bounds__(256) void kB(
    const int* __restrict__ mn, const float* __restrict__ H,
    const float* __restrict__ iw,
    const float* __restrict__ fc1w, const float* __restrict__ fc1b,
    const float* __restrict__ fc2w, const float* __restrict__ fc2b,
    const float* __restrict__ fc3w, const float* __restrict__ fc3b)
{
    int t = threadIdx.x;
    int w = t >> 5, lane = t & 31;
    int e = blockIdx.x * 8 + w;

    int   node = 0;
    float w2   = 0.f;
    if (lane < EDGESZ) {
        node = mn[e * EDGESZ + lane];
        atomicAdd(&g_deg[node], 1);
        float x0 = iw[node * 2 + 0];
        float x1 = iw[node * 2 + 1];
        float h1[10];
#pragma unroll
        for (int j = 0; j < 10; j++)
            h1[j] = fmaxf(0.f, fmaf(x0, fc1w[j], fmaf(x1, fc1w[10 + j], fc1b[j])));
        float h2[5];
#pragma unroll
        for (int j = 0; j < 5; j++) {
            float s = fc2b[j];
#pragma unroll
            for (int k = 0; k < 10; k++) s = fmaf(h1[k], fc2w[k * 5 + j], s);
            h2[j] = fmaxf(0.f, s);
        }
        float z = fc3b[0];
#pragma unroll
        for (int k = 0; k < 5; k++) z = fmaf(h2[k], fc3w[k], z);
        w2 = 1.f / (1.f + expf(-z));
    }

    const float4* H4 = reinterpret_cast<const float4*>(H);
    float4 s = make_float4(0.f, 0.f, 0.f, 0.f);
#pragma unroll
    for (int i = 0; i < EDGESZ; i++) {
        int   ni = __shfl_sync(0xffffffffu, node, i);
        float wi = __shfl_sync(0xffffffffu, w2,   i);
        float4 h = H4[(size_t)ni * (DIM / 4) + lane];
        s.x = __fadd_rn(s.x, __fmul_rn(h.x, wi));
        s.y = __fadd_rn(s.y, __fmul_rn(h.y, wi));
        s.z = __fadd_rn(s.z, __fmul_rn(h.z, wi));
        s.w = __fadd_rn(s.w, __fmul_rn(h.w, wi));
    }
    g_es4[(size_t)e * (DIM / 4) + lane] = s;
}

// ---------------------------------------------------------------------------
// Kernel Off: per-node segment offsets via warp-aggregated atomic counter
// ---------------------------------------------------------------------------
__global__ __launch_bounds__(256) void kOff()
{
    int n = blockIdx.x * 256 + threadIdx.x;
    int lane = threadIdx.x & 31;
    int deg = (n < NNODES) ? g_deg[n] : 0;
    int x = deg;
#pragma unroll
    for (int o = 1; o < 32; o <<= 1) {
        int y = __shfl_up_sync(0xffffffffu, x, o);
        if (lane >= o) x += y;
    }
    int total = __shfl_sync(0xffffffffu, x, 31);
    int base = 0;
    if (lane == 0) base = atomicAdd(&g_ctr, total);
    base = __shfl_sync(0xffffffffu, base, 0);
    if (n < NNODES) g_off[n] = base + x - deg;
}

// ---------------------------------------------------------------------------
// Scatter: node -> incident-edge list (edge id == membership >> 4).
// Arrival order racy; kF's stable sort makes the result deterministic.
// ---------------------------------------------------------------------------
__global__ __launch_bounds__(256) void kScat(const int* __restrict__ mn)
{
    int m = blockIdx.x * 256 + threadIdx.x;
    if (m >= NMEMB) return;
    int node = mn[m];
    int pos = g_off[node] + atomicAdd(&g_cnt[node], 1);
    g_elist[pos] = m >> 4;
}

// ---------------------------------------------------------------------------
// Kernel F: one WARP per node. STABLE register rank-sort of edge segment
// (duplicate edge ids possible when a node repeats within one edge — the
// (ej == e && j < lane) tie-break is load-bearing), 4-batched float4 gather
// per lane, double warp rowsum, AH store.
// grid = NNODES/8 blocks x 256 threads (8 warps)   <-- ncu launch index 3
// ---------------------------------------------------------------------------
__global__ __launch_bounds__(256) void kF(const float* __restrict__ H)
{
    __shared__ int ss[8 * 128];            // per-warp sorted edge ids
    int t = threadIdx.x;
    int w = t >> 5, lane = t & 31;
    int n = blockIdx.x * 8 + w;
    int* ssw = ss + w * 128;

    int deg = g_deg[n];
    int st  = g_off[n];
    const float inv15 = 1.f / 15.f;

    if (deg <= 32) {
        // stable register rank-sort via shuffles (duplicates get distinct ranks)
        int e = (lane < deg) ? g_elist[st + lane] : 0x7FFFFFFF;
        int rank = 0;
        for (int j = 0; j < deg; j++) {
            int ej = __shfl_sync(0xffffffffu, e, j);
            rank += (ej < e) || (ej == e && j < lane);
        }
        if (lane < deg) ssw[rank] = e;
    } else {
        // (practically unreachable) lane-0 insertion sort in smem (stable)
        if (lane == 0) {
            int d = deg < 128 ? deg : 128;
            for (int i = 0; i < d; i++) ssw[i] = g_elist[st + i];
            for (int i = 1; i < d; i++) {
                int key = ssw[i]; int j = i - 1;
                while (j >= 0 && ssw[j] > key) { ssw[j + 1] = ssw[j]; j--; }
                ssw[j + 1] = key;
            }
        }
    }
    __syncwarp();
    int dg = deg > 128 ? 128 : deg;

    // Gather in ascending-edge order. Loads batched 4-wide (independent);
    // per-column adds strictly sequential (bit-identical to R15/R16).
    float s0 = 0.f, s1 = 0.f, s2 = 0.f, s3 = 0.f;
    int j = 0;
    for (; j + 4 <= dg; j += 4) {
        float4 v0 = g_es4[(size_t)ssw[j + 0] * (DIM / 4) + lane];
        float4 v1 = g_es4[(size_t)ssw[j + 1] * (DIM / 4) + lane];
        float4 v2 = g_es4[(size_t)ssw[j + 2] * (DIM / 4) + lane];
        float4 v3 = g_es4[(size_t)ssw[j + 3] * (DIM / 4) + lane];
        s0 = __fadd_rn(__fadd_rn(__fadd_rn(__fadd_rn(s0, v0.x), v1.x), v2.x), v3.x);
        s1 = __fadd_rn(__fadd_rn(__fadd_rn(__fadd_rn(s1, v0.y), v1.y), v2.y), v3.y);
        s2 = __fadd_rn(__fadd_rn(__fadd_rn(__fadd_rn(s2, v0.z), v1.z), v2.z), v3.z);
        s3 = __fadd_rn(__fadd_rn(__fadd_rn(__fadd_rn(s3, v0.w), v1.w), v2.w), v3.w);
    }
    for (; j < dg; j++) {
        float4 v = g_es4[(size_t)ssw[j] * (DIM / 4) + lane];
        s0 = __fadd_rn(s0, v.x);
        s1 = __fadd_rn(s1, v.y);
        s2 = __fadd_rn(s2, v.z);
        s3 = __fadd_rn(s3, v.w);
    }

    float4 hv = reinterpret_cast<const float4*>(H)[(size_t)n * (DIM / 4) + lane];
    float coef = 1.f - (float)deg * inv15;
    float4 nv;
    nv.x = fmaf(hv.x, coef, s0 * inv15);
    nv.y = fmaf(hv.y, coef, s1 * inv15);
    nv.z = fmaf(hv.z, coef, s2 * inv15);
    nv.w = fmaf(hv.w, coef, s3 * inv15);

    // double-precision rowsum across the warp (order-insensitive at 1e-16)
    double d = ((double)nv.x + (double)nv.y) + ((double)nv.z + (double)nv.w);
#pragma unroll
    for (int o = 16; o > 0; o >>= 1)
        d += __shfl_xor_sync(0xffffffffu, d, o);
    float rinv = (d != 0.0) ? (float)(1.0 / d) : 0.f;

    float4 ov;
    ov.x = __fmul_rn(nv.x, rinv);
    ov.y = __fmul_rn(nv.y, rinv);
    ov.z = __fmul_rn(nv.z, rinv);
    ov.w = __fmul_rn(nv.w, rinv);
    g_AH4[(size_t)n * (DIM / 4) + lane] = ov;
}

// ---------------------------------------------------------------------------
// Kernel E: out = AH @ W + bias, packed f32x2 FFMA.
// block = 128 threads handles 32 rows; thread owns output column t.
// Epilogue re-zeroes deg/cnt/ctr for the next call.
// ---------------------------------------------------------------------------
__global__ __launch_bounds__(128) void kE(const float* __restrict__ W,
                                          const float* __restrict__ bias,
                                          float* __restrict__ out)
{
    __shared__ float4 sA4[32 * DIM / 4];
    float* sA = reinterpret_cast<float*>(sA4);
    int t = threadIdx.x;
    size_t base4 = (size_t)blockIdx.x * 32 * (DIM / 4);
#pragma unroll
    for (int i = 0; i < 8; i++) {
        int idx = i * 128 + t;                   // 0 .. 1023 float4s
        sA4[idx] = g_AH4[base4 + idx];
    }
    __syncthreads();

    unsigned long long acc[32];
#pragma unroll
    for (int i = 0; i < 32; i++) acc[i] = 0ull;

#pragma unroll 1
    for (int k = 0; k < DIM; k += 8) {
        unsigned long long wp0 = pk2(W[(k + 0) * DIM + t], W[(k + 1) * DIM + t]);
        unsigned long long wp1 = pk2(W[(k + 2) * DIM + t], W[(k + 3) * DIM + t]);
        unsigned long long wp2 = pk2(W[(k + 4) * DIM + t], W[(k + 5) * DIM + t]);
        unsigned long long wp3 = pk2(W[(k + 6) * DIM + t], W[(k + 7) * DIM + t]);
        const ulonglong2* arow = reinterpret_cast<const ulonglong2*>(sA + k);
#pragma unroll
        for (int i = 0; i < 32; i++) {
            ulonglong2 a0 = arow[i * (DIM / 4)];
            ulonglong2 a1 = arow[i * (DIM / 4) + 1];
            fma2(acc[i], a0.x, wp0);
            fma2(acc[i], a0.y, wp1);
            fma2(acc[i], a1.x, wp2);
            fma2(acc[i], a1.y, wp3);
        }
    }
    float b = bias[t];
    size_t obase = (size_t)blockIdx.x * 32 * DIM;
#pragma unroll
    for (int i = 0; i < 32; i++) {
        float lo, hi;
        unpk2(lo, hi, acc[i]);
        out[obase + (size_t)i * DIM + t] = lo + hi + b;
    }

    // Reset scratch counters for the next call (state invariant across calls)
    int gid = blockIdx.x * 128 + t;
    if (gid < NNODES) {
        g_deg[gid] = 0;
        g_cnt[gid] = 0;
    }
    if (gid == 0) g_ctr = 0;
}

// ---------------------------------------------------------------------------
extern "C" void kernel_launch(void* const* d_in, const int* in_sizes, int n_in,
                              void* d_out, int out_size)
{
    const int*   member_nodes = (const int*)  d_in[0];
    const float* H            = (const float*)d_in[2];
    const float* input_weight = (const float*)d_in[3];
    const float* W            = (const float*)d_in[4];
    const float* bias         = (const float*)d_in[5];
    const float* fc1_w        = (const float*)d_in[6];
    const float* fc1_b        = (const float*)d_in[7];
    const float* fc2_w        = (const float*)d_in[8];
    const float* fc2_b        = (const float*)d_in[9];
    const float* fc3_w        = (const float*)d_in[10];
    const float* fc3_b        = (const float*)d_in[11];
    float* out = (float*)d_out;

    kB<<<NEDGES / 8, 256>>>(member_nodes, H, input_weight,
                            fc1_w, fc1_b, fc2_w, fc2_b, fc3_w, fc3_b);
    kOff<<<(NNODES + 255) / 256, 256>>>();
    kScat<<<(NMEMB + 255) / 256, 256>>>(member_nodes);
    kF<<<NNODES / 8, 256>>>(H);                // launch index 3 -> ncu target
    kE<<<NNODES / 32, 128>>>(W, bias, out);
}